// round 1
// baseline (speedup 1.0000x reference)
#include <cuda_runtime.h>

// Problem constants (from reference: B=4096, H=300 (=z_dim), T=64)
#define BQ 4096
#define HD 300
#define FH (4 * HD)
#define TT 64

// Ping-pong hidden states (read by all CTAs while being rewritten -> double buffer).
// Cell states are owner-exclusive -> in-place.
__device__ __align__(128) float g_h0[2][BQ * HD];
__device__ __align__(128) float g_c0[BQ * HD];
__device__ __align__(128) float g_h1[2][BQ * HD];
__device__ __align__(128) float g_c1[BQ * HD];

__global__ void zero_kernel(float* __restrict__ p, int n) {
    int i = blockIdx.x * blockDim.x + threadIdx.x;
    int stride = gridDim.x * blockDim.x;
    for (; i < n; i += stride) p[i] = 0.0f;
}

// One fused LSTM cell: gates = X @ Wih^T + Hin @ Whh^T + (bih+bhh); update c,h.
// Tiling: CTA = 128 batch rows x 32 hidden units (=128 gate columns), K = 600.
// Gate-column interleave: n -> unit j0 + (n>>2), gate (n&3). Each thread's 8
// accumulator columns = 2 units x 4 gates -> full cell update stays thread-local.
__global__ __launch_bounds__(256, 2)
void lstm_cell_kernel(const float* __restrict__ X,
                      const float* __restrict__ Hin,
                      float* __restrict__ C,
                      float* __restrict__ Hout,
                      const float* __restrict__ Wih,
                      const float* __restrict__ Whh,
                      const float* __restrict__ bih,
                      const float* __restrict__ bhh,
                      float* __restrict__ Y)  // == out + t*HD, or nullptr
{
    __shared__ float As[8][128];   // [k][m]
    __shared__ float Bs[8][128];   // [k][n]

    const int tid = threadIdx.x;
    const int tx = tid & 15;       // 0..15 -> 8 gate columns
    const int ty = tid >> 4;       // 0..15 -> 8 batch rows
    const int m0 = blockIdx.y * 128;
    const int j0 = blockIdx.x * 32;

    // Global-load assignment: each thread loads one float4 of A and of B per K-tile.
    const int lm = tid >> 1;           // 0..127
    const int lk = (tid & 1) * 4;      // 0 or 4

    // B (= W^T) column lm maps to W row: gate (lm&3), unit j0 + (lm>>2)
    const int bu = j0 + (lm >> 2);
    const int bg = lm & 3;
    const bool bvalid = (bu < HD);
    const long brow = (long)(bg * HD + bu) * HD;

    float acc[8][8];
#pragma unroll
    for (int i = 0; i < 8; ++i)
#pragma unroll
        for (int j = 0; j < 8; ++j) acc[i][j] = 0.0f;

    // Bias per thread-column (same across rows)
    float bias[8];
#pragma unroll
    for (int jj = 0; jj < 8; ++jj) {
        int n = tx * 8 + jj;
        int u = j0 + (n >> 2);
        int g = n & 3;
        bias[jj] = (u < HD) ? (bih[g * HD + u] + bhh[g * HD + u]) : 0.0f;
    }

#pragma unroll 1
    for (int part = 0; part < 2; ++part) {
        const float* Ag = part ? Hin : X;
        const float* Wg = part ? Whh : Wih;
#pragma unroll 1
        for (int k0 = 0; k0 < HD; k0 += 8) {
            // K = 300 is not a multiple of 8: last tile's upper half (k>=300) is zero.
            const bool kvalid = (k0 + lk) < HD;
            float4 a4 = make_float4(0.f, 0.f, 0.f, 0.f);
            float4 b4 = make_float4(0.f, 0.f, 0.f, 0.f);
            if (kvalid) {
                a4 = *(const float4*)(Ag + (long)(m0 + lm) * HD + k0 + lk);
                if (bvalid) b4 = *(const float4*)(Wg + brow + k0 + lk);
            }
            As[lk + 0][lm] = a4.x; As[lk + 1][lm] = a4.y;
            As[lk + 2][lm] = a4.z; As[lk + 3][lm] = a4.w;
            Bs[lk + 0][lm] = b4.x; Bs[lk + 1][lm] = b4.y;
            Bs[lk + 2][lm] = b4.z; Bs[lk + 3][lm] = b4.w;
            __syncthreads();

#pragma unroll
            for (int kk = 0; kk < 8; ++kk) {
                float ar[8], br[8];
                *(float4*)&ar[0] = *(const float4*)&As[kk][ty * 8 + 0];
                *(float4*)&ar[4] = *(const float4*)&As[kk][ty * 8 + 4];
                *(float4*)&br[0] = *(const float4*)&Bs[kk][tx * 8 + 0];
                *(float4*)&br[4] = *(const float4*)&Bs[kk][tx * 8 + 4];
#pragma unroll
                for (int i = 0; i < 8; ++i)
#pragma unroll
                    for (int j = 0; j < 8; ++j)
                        acc[i][j] = fmaf(ar[i], br[j], acc[i][j]);
            }
            __syncthreads();
        }
    }

    // Epilogue: per (row, unit) full LSTM update. PyTorch gate order i,f,g,o.
#pragma unroll
    for (int i = 0; i < 8; ++i) {
        const long b = m0 + ty * 8 + i;
#pragma unroll
        for (int uu = 0; uu < 2; ++uu) {
            const int u = j0 + tx * 2 + uu;
            if (u >= HD) continue;
            const float iv = acc[i][uu * 4 + 0] + bias[uu * 4 + 0];
            const float fv = acc[i][uu * 4 + 1] + bias[uu * 4 + 1];
            const float gv = acc[i][uu * 4 + 2] + bias[uu * 4 + 2];
            const float ov = acc[i][uu * 4 + 3] + bias[uu * 4 + 3];
            const float ig = 1.0f / (1.0f + __expf(-iv));
            const float fg = 1.0f / (1.0f + __expf(-fv));
            const float gg = tanhf(gv);
            const float og = 1.0f / (1.0f + __expf(-ov));
            const long idx = b * HD + u;
            const float cn = fg * C[idx] + ig * gg;
            const float hn = og * tanhf(cn);
            C[idx] = cn;
            Hout[idx] = hn;
            if (Y) Y[b * (long)(TT * HD) + u] = hn;
        }
    }
}

extern "C" void kernel_launch(void* const* d_in, const int* in_sizes, int n_in,
                              void* d_out, int out_size) {
    const float* z    = (const float*)d_in[0];
    const float* Wih0 = (const float*)d_in[1];
    const float* Whh0 = (const float*)d_in[2];
    const float* bih0 = (const float*)d_in[3];
    const float* bhh0 = (const float*)d_in[4];
    const float* Wih1 = (const float*)d_in[5];
    const float* Whh1 = (const float*)d_in[6];
    const float* bih1 = (const float*)d_in[7];
    const float* bhh1 = (const float*)d_in[8];
    float* out = (float*)d_out;

    float *h0, *c0, *h1, *c1;
    cudaGetSymbolAddress((void**)&h0, g_h0);
    cudaGetSymbolAddress((void**)&c0, g_c0);
    cudaGetSymbolAddress((void**)&h1, g_h1);
    cudaGetSymbolAddress((void**)&c1, g_c1);

    const int n = BQ * HD;
    zero_kernel<<<592, 256>>>(h0, n);       // h0[0]
    zero_kernel<<<592, 256>>>(h1, n);       // h1[0]
    zero_kernel<<<592, 256>>>(c0, n);
    zero_kernel<<<592, 256>>>(c1, n);

    // Grid: 10 unit-tiles (ceil(300/32)) x 32 batch-tiles
    dim3 grid(10, 32);
    for (int t = 0; t < TT; ++t) {
        const int p = t & 1;
        const float* x0 = t ? (h1 + p * n) : z;
        // Layer 0: reads h0[p], writes h0[p^1]; c0 in place.
        lstm_cell_kernel<<<grid, 256>>>(x0, h0 + p * n, c0, h0 + (p ^ 1) * n,
                                        Wih0, Whh0, bih0, bhh0, nullptr);
        // Layer 1: x = fresh h0; reads h1[p], writes h1[p^1]; c1 in place; emits out[:, t, :].
        lstm_cell_kernel<<<grid, 256>>>(h0 + (p ^ 1) * n, h1 + p * n, c1, h1 + (p ^ 1) * n,
                                        Wih1, Whh1, bih1, bhh1, out + (long)t * HD);
    }
}